// round 11
// baseline (speedup 1.0000x reference)
#include <cuda_runtime.h>
#include <cuda_bf16.h>
#include <cstdint>

#define SEQ 2048
#define NB  4
#define DM  1024
#define DP  256

// ---------------- bf16-split scratch -----------------------------------------
__device__ __nv_bfloat16 g_w_hi[DP * DM];                   // 512 KB
__device__ __nv_bfloat16 g_w_lo[DP * DM];                   // 512 KB
__device__ __nv_bfloat16 g_h_hi[(size_t)NB * SEQ * DP];     // 4 MB
__device__ __nv_bfloat16 g_h_lo[(size_t)NB * SEQ * DP];     // 4 MB

// ============================ PTX helpers ====================================
__device__ __forceinline__ uint32_t smem_u32(const void* p) {
    uint32_t a;
    asm("{ .reg .u64 t; cvta.to.shared.u64 t, %1; cvt.u32.u64 %0, t; }" : "=r"(a) : "l"(p));
    return a;
}
__device__ __forceinline__ void cp16(uint32_t s, const void* g) {
    asm volatile("cp.async.cg.shared.global [%0], [%1], 16;" :: "r"(s), "l"(g));
}
#define CP_COMMIT() asm volatile("cp.async.commit_group;" ::: "memory")
#define CP_WAIT1()  asm volatile("cp.async.wait_group 1;"  ::: "memory")
#define CP_WAIT0()  asm volatile("cp.async.wait_group 0;"  ::: "memory")

__device__ __forceinline__ void ldsm4(uint32_t* r, uint32_t addr) {
    asm volatile("ldmatrix.sync.aligned.m8n8.x4.shared.b16 {%0,%1,%2,%3}, [%4];"
                 : "=r"(r[0]), "=r"(r[1]), "=r"(r[2]), "=r"(r[3]) : "r"(addr));
}
__device__ __forceinline__ void mma_bf16(float* d, const uint32_t* a, const uint32_t* b) {
    asm volatile("mma.sync.aligned.m16n8k16.row.col.f32.bf16.bf16.f32 "
                 "{%0,%1,%2,%3}, {%4,%5,%6,%7}, {%8,%9}, {%0,%1,%2,%3};"
                 : "+f"(d[0]), "+f"(d[1]), "+f"(d[2]), "+f"(d[3])
                 : "r"(a[0]), "r"(a[1]), "r"(a[2]), "r"(a[3]), "r"(b[0]), "r"(b[1]));
}

// swizzled in-tile byte offset (row stride 64B, 4x16B cells per row)
#define SWZ(row, c16) ((uint32_t)((row) * 64) + ((uint32_t)((c16) ^ (((row) >> 1) & 3)) << 4))

// -------- generic K=32 compute chunk, warp tile (FM*16) x 32 -----------------
template<int FM>
__device__ __forceinline__ void compute_chunk(
    uint32_t sbase, uint32_t offAH, uint32_t offAL, uint32_t offBH, uint32_t offBL,
    int lid, int mwarp, int nwarp, float acc[FM][4][4])
{
    const int rA = mwarp + (lid & 15);
    const int xA = (rA >> 1) & 3;
    const int cA = (lid >> 4);
    const int rB = nwarp + ((lid >> 4) << 3) + (lid & 7);
    const int xB = (rB >> 1) & 3;
    const int cB = (lid >> 3) & 1;

#pragma unroll
    for (int kk = 0; kk < 2; kk++) {
        uint32_t bh[2][4], bl[2][4];
#pragma unroll
        for (int p = 0; p < 2; p++) {
            const uint32_t base = sbase + (uint32_t)((rB + p * 16) * 64)
                                + ((uint32_t)((kk * 2 + cB) ^ xB) << 4);
            ldsm4(bh[p], base + offBH);
            ldsm4(bl[p], base + offBL);
        }
#pragma unroll
        for (int fm = 0; fm < FM; fm++) {
            uint32_t ah[4], al[4];
            const uint32_t base = sbase + (uint32_t)((rA + fm * 16) * 64)
                                + ((uint32_t)((kk * 2 + cA) ^ xA) << 4);
            ldsm4(ah, base + offAH);
            ldsm4(al, base + offAL);
#pragma unroll
            for (int fn = 0; fn < 4; fn++) {
                const uint32_t* bhp = &bh[fn >> 1][(fn & 1) * 2];
                const uint32_t* blp = &bl[fn >> 1][(fn & 1) * 2];
                mma_bf16(acc[fm][fn], ah, bhp);
                mma_bf16(acc[fm][fn], ah, blp);
                mma_bf16(acc[fm][fn], al, bhp);
            }
        }
    }
}

// ======================= split conversion kernel (W only) ====================
__global__ __launch_bounds__(256) void split_kernel(
    const float* __restrict__ src, __nv_bfloat16* __restrict__ hi,
    __nv_bfloat16* __restrict__ lo)
{
#pragma unroll
    for (int q = 0; q < 4; q++) {
        const size_t i = (size_t)q * 16384 + blockIdx.x * 256 + threadIdx.x;
        float4 v = reinterpret_cast<const float4*>(src)[i];
        float f[4] = {v.x, v.y, v.z, v.w};
        __nv_bfloat16 hb[4], lb[4];
#pragma unroll
        for (int j = 0; j < 4; j++) {
            hb[j] = __float2bfloat16(f[j]);
            lb[j] = __float2bfloat16(f[j] - __bfloat162float(hb[j]));
        }
        reinterpret_cast<__nv_bfloat162*>(hi)[i * 2 + 0] = __nv_bfloat162(hb[0], hb[1]);
        reinterpret_cast<__nv_bfloat162*>(hi)[i * 2 + 1] = __nv_bfloat162(hb[2], hb[3]);
        reinterpret_cast<__nv_bfloat162*>(lo)[i * 2 + 0] = __nv_bfloat162(lb[0], lb[1]);
        reinterpret_cast<__nv_bfloat162*>(lo)[i * 2 + 1] = __nv_bfloat162(lb[2], lb[3]);
    }
}

// =============================================================================
// GEMM1: h = relu(hidden @ W^T + bias).  Fp32 A via pipelined LDG, converted to
// bf16 hi/lo at STS time.  Tile 64M x 128N, 8 warps (32x32), 3-stage ring.
// =============================================================================
#define P_AH 0
#define P_AL 4096
#define P_BH 8192
#define P_BL 16384
#define P_STAGE 24576          // 24 KB; 3 stages = 72 KB

__global__ __launch_bounds__(256, 2) void proj_kernel(
    const float* __restrict__ A, const float* __restrict__ bias)
{
    extern __shared__ char sm[];
    const uint32_t sbase = smem_u32(sm);
    const int tid = threadIdx.x, lid = tid & 31, wid = tid >> 5;
    const int mwarp = (wid >> 2) * 32, nwarp = (wid & 3) * 32;
    const int m0 = blockIdx.y * 64, n0 = blockIdx.x * 128;

    const float* Ag = A + (size_t)m0 * DM;
    const __nv_bfloat16* Wh = g_w_hi + (size_t)n0 * DM;
    const __nv_bfloat16* Wl = g_w_lo + (size_t)n0 * DM;

    // this thread's A cell: row ar, 16B-cell ac (64 rows x 4 cells = 256 cells)
    const int ar = tid >> 2;
    const int ac = tid & 3;
    const uint32_t aswz = SWZ(ar, ac);
    const float* agp = Ag + (size_t)ar * DM + ac * 8;

    float acc[2][4][4];
#pragma unroll
    for (int a = 0; a < 2; a++)
#pragma unroll
        for (int b = 0; b < 4; b++)
#pragma unroll
            for (int c = 0; c < 4; c++) acc[a][b][c] = 0.0f;

    const int NC = DM / 32;

    // --- helpers (lambdas keep reg lifetimes tight) ---
    auto fillW = [&](int chunk) {
        const uint32_t st = sbase + (uint32_t)(chunk % 3) * P_STAGE;
        const int kb = chunk * 32;
#pragma unroll
        for (int i = 0; i < 2; i++) {
            const int idx = tid + i * 256, r = idx >> 2, c16 = idx & 3;
            const uint32_t sw = SWZ(r, c16);
            const size_t go = (size_t)r * DM + kb + c16 * 8;
            cp16(st + P_BH + sw, Wh + go);
            cp16(st + P_BL + sw, Wl + go);
        }
        CP_COMMIT();
    };
    auto stsA = [&](int chunk, const float4& f0, const float4& f1) {
        float f[8] = {f0.x, f0.y, f0.z, f0.w, f1.x, f1.y, f1.z, f1.w};
        union { __nv_bfloat16 b[8]; uint4 u; } hv, lv;
#pragma unroll
        for (int j = 0; j < 8; j++) {
            const __nv_bfloat16 h = __float2bfloat16(f[j]);
            hv.b[j] = h;
            lv.b[j] = __float2bfloat16(f[j] - __bfloat162float(h));
        }
        char* st = sm + (chunk % 3) * P_STAGE;
        *reinterpret_cast<uint4*>(st + P_AH + aswz) = hv.u;
        *reinterpret_cast<uint4*>(st + P_AL + aswz) = lv.u;
    };

    // --- prologue: stages 0,1 fully filled; A(2) regs in flight ---
    float4 fa0[2], fa1[2];
    fa0[0] = *reinterpret_cast<const float4*>(agp);
    fa1[0] = *reinterpret_cast<const float4*>(agp + 4);
    fa0[1] = *reinterpret_cast<const float4*>(agp + 32);
    fa1[1] = *reinterpret_cast<const float4*>(agp + 36);
    fillW(0);
    fillW(1);
    stsA(0, fa0[0], fa1[0]);
    stsA(1, fa0[1], fa1[1]);
    fa0[0] = *reinterpret_cast<const float4*>(agp + 64);   // A(2)
    fa1[0] = *reinterpret_cast<const float4*>(agp + 68);

    for (int c = 0; c < NC; c++) {
        if (c + 2 < NC) CP_WAIT1(); else CP_WAIT0();
        __syncthreads();
        if (c + 2 < NC) {
            fillW(c + 2);
            const int pb = c & 1;            // buffer holding A(c+2)
            if (c + 3 < NC) {                // start A(c+3) LDG
                const int kb = (c + 3) * 32;
                fa0[pb ^ 1] = *reinterpret_cast<const float4*>(agp + kb);
                fa1[pb ^ 1] = *reinterpret_cast<const float4*>(agp + kb + 4);
            }
            stsA(c + 2, fa0[pb], fa1[pb]);
        }
        compute_chunk<2>(sbase + (uint32_t)(c % 3) * P_STAGE,
                         P_AH, P_AL, P_BH, P_BL, lid, mwarp, nwarp, acc);
    }

    // epilogue: bias + relu + bf16 hi/lo split store
    const int g = lid >> 2, t = lid & 3;
#pragma unroll
    for (int fn = 0; fn < 4; fn++) {
        const int col = n0 + nwarp + fn * 8 + t * 2;
        const float2 bv = *reinterpret_cast<const float2*>(bias + col);
#pragma unroll
        for (int fm = 0; fm < 2; fm++) {
            const int row = m0 + mwarp + fm * 16 + g;
#pragma unroll
            for (int h = 0; h < 2; h++) {
                float x = acc[fm][fn][h * 2 + 0] + bv.x;
                float y = acc[fm][fn][h * 2 + 1] + bv.y;
                x = fmaxf(x, 0.0f); y = fmaxf(y, 0.0f);
                const __nv_bfloat16 xh = __float2bfloat16(x);
                const __nv_bfloat16 yh = __float2bfloat16(y);
                const __nv_bfloat16 xl = __float2bfloat16(x - __bfloat162float(xh));
                const __nv_bfloat16 yl = __float2bfloat16(y - __bfloat162float(yh));
                const size_t o = (size_t)(row + h * 8) * DP + col;
                *reinterpret_cast<__nv_bfloat162*>(g_h_hi + o) = __nv_bfloat162(xh, yh);
                *reinterpret_cast<__nv_bfloat162*>(g_h_lo + o) = __nv_bfloat162(xl, yl);
            }
        }
    }
}

// =============================================================================
// GEMM2: out[b][i][j] = (h_i . h_j)*clf_w + clf_b.  Tile 128x128, 8 warps
// (64x32), 3-stage ring, triangular tile pairs + smem-transposed mirror.
// =============================================================================
#define S_TILE  8192
#define S_AH    0
#define S_AL    S_TILE
#define S_BH    (2 * S_TILE)
#define S_BL    (3 * S_TILE)
#define S_STAGE (4 * S_TILE)   // 32 KB; 3 stages = 96 KB

__global__ __launch_bounds__(256, 2) void scores_kernel(
    const float* __restrict__ clf_w, const float* __restrict__ clf_b,
    float* __restrict__ out)
{
    extern __shared__ char sm[];
    const uint32_t sbase = smem_u32(sm);
    const int tid = threadIdx.x, lid = tid & 31, wid = tid >> 5;
    const int mwarp = (wid >> 2) * 64, nwarp = (wid & 3) * 32;
    const int bat = blockIdx.y;

    int tt = blockIdx.x, bi = 0;
    while (tt >= 16 - bi) { tt -= 16 - bi; bi++; }
    const int bj = bi + tt;

    const size_t hb = (size_t)bat * SEQ * DP;
    const __nv_bfloat16* Ah = g_h_hi + hb + (size_t)bi * 128 * DP;
    const __nv_bfloat16* Al = g_h_lo + hb + (size_t)bi * 128 * DP;
    const __nv_bfloat16* Bh = g_h_hi + hb + (size_t)bj * 128 * DP;
    const __nv_bfloat16* Bl = g_h_lo + hb + (size_t)bj * 128 * DP;

    float acc[4][4][4];
#pragma unroll
    for (int a = 0; a < 4; a++)
#pragma unroll
        for (int b = 0; b < 4; b++)
#pragma unroll
            for (int c = 0; c < 4; c++) acc[a][b][c] = 0.0f;

    auto fill = [&](int chunk) {
        const uint32_t st = sbase + (uint32_t)(chunk % 3) * S_STAGE;
        const int kb = chunk * 32;
#pragma unroll
        for (int i = 0; i < 2; i++) {
            const int idx = tid + i * 256;
            const int r = idx >> 2, c16 = idx & 3;
            const uint32_t sw = SWZ(r, c16);
            const size_t go = (size_t)r * DP + kb + c16 * 8;
            cp16(st + S_AH + sw, Ah + go);
            cp16(st + S_AL + sw, Al + go);
            cp16(st + S_BH + sw, Bh + go);
            cp16(st + S_BL + sw, Bl + go);
        }
        CP_COMMIT();
    };

    const int NC = DP / 32;   // 8
    fill(0);
    fill(1);
    for (int c = 0; c < NC; c++) {
        if (c + 2 < NC) CP_WAIT1(); else CP_WAIT0();
        __syncthreads();
        if (c + 2 < NC) fill(c + 2);
        compute_chunk<4>(sbase + (uint32_t)(c % 3) * S_STAGE,
                         S_AH, S_AL, S_BH, S_BL, lid, mwarp, nwarp, acc);
    }

    const float scale = clf_w[0];
    const float beta  = clf_b[0];
    float* C = out + (size_t)bat * SEQ * SEQ;
    float (*Cs)[129] = reinterpret_cast<float (*)[129]>(sm);

    __syncthreads();   // reuse smem as Cs

    const int g = lid >> 2, t = lid & 3;
#pragma unroll
    for (int fm = 0; fm < 4; fm++)
#pragma unroll
        for (int fn = 0; fn < 4; fn++) {
            const int rl = mwarp + fm * 16 + g;
            const int cl = nwarp + fn * 8 + t * 2;
            const float v0 = acc[fm][fn][0] * scale + beta;
            const float v1 = acc[fm][fn][1] * scale + beta;
            const float v2 = acc[fm][fn][2] * scale + beta;
            const float v3 = acc[fm][fn][3] * scale + beta;
            *reinterpret_cast<float2*>(C + (size_t)(bi * 128 + rl) * SEQ + bj * 128 + cl)
                = make_float2(v0, v1);
            *reinterpret_cast<float2*>(C + (size_t)(bi * 128 + rl + 8) * SEQ + bj * 128 + cl)
                = make_float2(v2, v3);
            if (bi != bj) {
                Cs[rl][cl] = v0; Cs[rl][cl + 1] = v1;
                Cs[rl + 8][cl] = v2; Cs[rl + 8][cl + 1] = v3;
            }
        }

    if (bi != bj) {
        __syncthreads();
#pragma unroll 4
        for (int e = 0; e < 64; e++) {
            const int idx  = e * 256 + tid;
            const int cloc = idx >> 7;
            const int rloc = idx & 127;
            C[(size_t)(bj * 128 + cloc) * SEQ + bi * 128 + rloc] = Cs[rloc][cloc];
        }
    }
}

// =============================================================================
extern "C" void kernel_launch(void* const* d_in, const int* in_sizes, int n_in,
                              void* d_out, int out_size)
{
    const float* hidden = (const float*)d_in[0];
    const float* proj_w = (const float*)d_in[1];
    const float* proj_b = (const float*)d_in[2];
    const float* clf_w  = (const float*)d_in[3];
    const float* clf_b  = (const float*)d_in[4];
    float* out = (float*)d_out;

    __nv_bfloat16 *w_hi, *w_lo;
    cudaGetSymbolAddress((void**)&w_hi, g_w_hi);
    cudaGetSymbolAddress((void**)&w_lo, g_w_lo);

    split_kernel<<<64, 256>>>(proj_w, w_hi, w_lo);

    const int smem_proj = 3 * P_STAGE;        // 72 KB
    const int smem_sc   = 3 * S_STAGE;        // 96 KB (covers 66 KB Cs alias)
    cudaFuncSetAttribute(proj_kernel,
                         cudaFuncAttributeMaxDynamicSharedMemorySize, smem_proj);
    cudaFuncSetAttribute(scores_kernel,
                         cudaFuncAttributeMaxDynamicSharedMemorySize, smem_sc);

    dim3 g1(DP / 128, (NB * SEQ) / 64);       // (2, 128) = 256 CTAs
    proj_kernel<<<g1, 256, smem_proj>>>(hidden, proj_b);

    dim3 g2(136, NB);
    scores_kernel<<<g2, 256, smem_sc>>>(clf_w, clf_b, out);
}

// round 14
// speedup vs baseline: 1.1569x; 1.1569x over previous
#include <cuda_runtime.h>
#include <cuda_bf16.h>
#include <cstdint>

#define SEQ 2048
#define NB  4
#define DM  1024
#define DP  256

// ---------------- bf16-split scratch -----------------------------------------
__device__ __nv_bfloat16 g_w_hi[DP * DM];                   // 512 KB
__device__ __nv_bfloat16 g_w_lo[DP * DM];                   // 512 KB
__device__ __nv_bfloat16 g_h_hi[(size_t)NB * SEQ * DP];     // 4 MB
__device__ __nv_bfloat16 g_h_lo[(size_t)NB * SEQ * DP];     // 4 MB

// ============================ PTX helpers ====================================
__device__ __forceinline__ uint32_t smem_u32(const void* p) {
    uint32_t a;
    asm("{ .reg .u64 t; cvta.to.shared.u64 t, %1; cvt.u32.u64 %0, t; }" : "=r"(a) : "l"(p));
    return a;
}
__device__ __forceinline__ void cp16(uint32_t s, const void* g) {
    asm volatile("cp.async.cg.shared.global [%0], [%1], 16;" :: "r"(s), "l"(g));
}
#define CP_COMMIT() asm volatile("cp.async.commit_group;" ::: "memory")
#define CP_WAIT1()  asm volatile("cp.async.wait_group 1;"  ::: "memory")
#define CP_WAIT0()  asm volatile("cp.async.wait_group 0;"  ::: "memory")

__device__ __forceinline__ void ldsm4(uint32_t* r, uint32_t addr) {
    asm volatile("ldmatrix.sync.aligned.m8n8.x4.shared.b16 {%0,%1,%2,%3}, [%4];"
                 : "=r"(r[0]), "=r"(r[1]), "=r"(r[2]), "=r"(r[3]) : "r"(addr));
}
__device__ __forceinline__ void mma_bf16(float* d, const uint32_t* a, const uint32_t* b) {
    asm volatile("mma.sync.aligned.m16n8k16.row.col.f32.bf16.bf16.f32 "
                 "{%0,%1,%2,%3}, {%4,%5,%6,%7}, {%8,%9}, {%0,%1,%2,%3};"
                 : "+f"(d[0]), "+f"(d[1]), "+f"(d[2]), "+f"(d[3])
                 : "r"(a[0]), "r"(a[1]), "r"(a[2]), "r"(a[3]), "r"(b[0]), "r"(b[1]));
}

// 64B-row swizzle (scores tiles: 4x16B cells per row)
#define SWZ(row, c16) ((uint32_t)((row) * 64) + ((uint32_t)((c16) ^ (((row) >> 1) & 3)) << 4))
// 128B-row swizzle (proj tiles: 8x16B cells per row)
#define SWZ128(row, c16) ((uint32_t)((row) * 128) + ((uint32_t)((c16) ^ ((row) & 7)) << 4))

// ======================= split conversion kernel (W only) ====================
__global__ __launch_bounds__(256) void split_kernel(
    const float* __restrict__ src, __nv_bfloat16* __restrict__ hi,
    __nv_bfloat16* __restrict__ lo)
{
#pragma unroll
    for (int q = 0; q < 4; q++) {
        const size_t i = (size_t)q * 16384 + blockIdx.x * 256 + threadIdx.x;
        float4 v = reinterpret_cast<const float4*>(src)[i];
        float f[4] = {v.x, v.y, v.z, v.w};
        __nv_bfloat16 hb[4], lb[4];
#pragma unroll
        for (int j = 0; j < 4; j++) {
            hb[j] = __float2bfloat16(f[j]);
            lb[j] = __float2bfloat16(f[j] - __bfloat162float(hb[j]));
        }
        reinterpret_cast<__nv_bfloat162*>(hi)[i * 2 + 0] = __nv_bfloat162(hb[0], hb[1]);
        reinterpret_cast<__nv_bfloat162*>(hi)[i * 2 + 1] = __nv_bfloat162(hb[2], hb[3]);
        reinterpret_cast<__nv_bfloat162*>(lo)[i * 2 + 0] = __nv_bfloat162(lb[0], lb[1]);
        reinterpret_cast<__nv_bfloat162*>(lo)[i * 2 + 1] = __nv_bfloat162(lb[2], lb[3]);
    }
}

// =============================================================================
// GEMM1: h = relu(hidden @ W^T + bias).  Fp32 A via LDG (1-deep prefetch),
// converted to bf16 hi/lo at STS time.  Tile 64M x 128N, 8 warps (32x32).
// K-chunk 64 (128B swizzled rows), 2-stage, 2 syncs/chunk.  NC = 16.
// =============================================================================
#define P_AH 0
#define P_AL 8192
#define P_BH 16384
#define P_BL 32768
#define P_STAGE 49152          // 48 KB; 2 stages = 96 KB

__global__ __launch_bounds__(256, 2) void proj_kernel(
    const float* __restrict__ A, const float* __restrict__ bias)
{
    extern __shared__ char sm[];
    const uint32_t sbase = smem_u32(sm);
    const int tid = threadIdx.x, lid = tid & 31, wid = tid >> 5;
    const int mwarp = (wid >> 2) * 32, nwarp = (wid & 3) * 32;
    const int m0 = blockIdx.y * 64, n0 = blockIdx.x * 128;

    const float* Ag = A + (size_t)m0 * DM;
    const __nv_bfloat16* Wh = g_w_hi + (size_t)n0 * DM;
    const __nv_bfloat16* Wl = g_w_lo + (size_t)n0 * DM;

    // this thread's 2 A cells: (r0,c0) = tid, (r1,c1) = tid+256 of 64x8 cells
    const int ar0 = tid >> 3,        ac0 = tid & 7;
    const int ar1 = (tid + 256) >> 3, ac1 = (tid + 256) & 7;
    const uint32_t asw0 = SWZ128(ar0, ac0);
    const uint32_t asw1 = SWZ128(ar1, ac1);
    const float* agp0 = Ag + (size_t)ar0 * DM + ac0 * 8;
    const float* agp1 = Ag + (size_t)ar1 * DM + ac1 * 8;

    float acc[2][4][4];
#pragma unroll
    for (int a = 0; a < 2; a++)
#pragma unroll
        for (int b = 0; b < 4; b++)
#pragma unroll
            for (int c = 0; c < 4; c++) acc[a][b][c] = 0.0f;

    const int NC = DM / 64;   // 16

    auto fillW = [&](int chunk) {
        const uint32_t st = sbase + (uint32_t)(chunk & 1) * P_STAGE;
        const int kb = chunk * 64;
#pragma unroll
        for (int i = 0; i < 4; i++) {
            const int idx = tid + i * 256, r = idx >> 3, c = idx & 7;
            const uint32_t sw = SWZ128(r, c);
            const size_t go = (size_t)r * DM + kb + c * 8;
            cp16(st + P_BH + sw, Wh + go);
            cp16(st + P_BL + sw, Wl + go);
        }
        CP_COMMIT();
    };

    // A regs: 4 float4 = 16 floats (two cells x 8 floats)
    float4 fa[4];
    auto ldgA = [&](int chunk) {
        const int kb = chunk * 64;
        fa[0] = *reinterpret_cast<const float4*>(agp0 + kb);
        fa[1] = *reinterpret_cast<const float4*>(agp0 + kb + 4);
        fa[2] = *reinterpret_cast<const float4*>(agp1 + kb);
        fa[3] = *reinterpret_cast<const float4*>(agp1 + kb + 4);
    };
    auto stsA = [&](int chunk) {
        char* st = sm + (chunk & 1) * P_STAGE;
#pragma unroll
        for (int cell = 0; cell < 2; cell++) {
            const float4 f0 = fa[cell * 2], f1 = fa[cell * 2 + 1];
            float f[8] = {f0.x, f0.y, f0.z, f0.w, f1.x, f1.y, f1.z, f1.w};
            union { __nv_bfloat16 b[8]; uint4 u; } hv, lv;
#pragma unroll
            for (int j = 0; j < 8; j++) {
                const __nv_bfloat16 h = __float2bfloat16(f[j]);
                hv.b[j] = h;
                lv.b[j] = __float2bfloat16(f[j] - __bfloat162float(h));
            }
            const uint32_t sw = cell ? asw1 : asw0;
            *reinterpret_cast<uint4*>(st + P_AH + sw) = hv.u;
            *reinterpret_cast<uint4*>(st + P_AL + sw) = lv.u;
        }
    };

    // fragment addressing constants
    const int rA = mwarp + (lid & 15), xA = rA & 7, cA = lid >> 4;
    const int rB = nwarp + ((lid >> 4) << 3) + (lid & 7), xB = rB & 7;
    const int cB = (lid >> 3) & 1;

    // prologue
    ldgA(0);
    fillW(0);

    for (int c = 0; c < NC; c++) {
        stsA(c);
        if (c + 1 < NC) {
            ldgA(c + 1);
            fillW(c + 1);
            CP_WAIT1();
        } else {
            CP_WAIT0();
        }
        __syncthreads();

        const uint32_t buf = sbase + (uint32_t)(c & 1) * P_STAGE;
#pragma unroll
        for (int kk = 0; kk < 4; kk++) {
            uint32_t bh[2][4], bl[2][4];
#pragma unroll
            for (int p = 0; p < 2; p++) {
                const uint32_t base = buf + (uint32_t)((rB + p * 16) * 128)
                                    + ((uint32_t)((kk * 2 + cB) ^ xB) << 4);
                ldsm4(bh[p], base + P_BH);
                ldsm4(bl[p], base + P_BL);
            }
#pragma unroll
            for (int fm = 0; fm < 2; fm++) {
                uint32_t ah[4], al[4];
                const uint32_t base = buf + (uint32_t)((rA + fm * 16) * 128)
                                    + ((uint32_t)((kk * 2 + cA) ^ xA) << 4);
                ldsm4(ah, base + P_AH);
                ldsm4(al, base + P_AL);
#pragma unroll
                for (int fn = 0; fn < 4; fn++) {
                    const uint32_t* bhp = &bh[fn >> 1][(fn & 1) * 2];
                    const uint32_t* blp = &bl[fn >> 1][(fn & 1) * 2];
                    mma_bf16(acc[fm][fn], ah, bhp);
                    mma_bf16(acc[fm][fn], ah, blp);
                    mma_bf16(acc[fm][fn], al, bhp);
                }
            }
        }
        __syncthreads();
    }

    // epilogue: bias + relu + bf16 hi/lo split store
    const int g = lid >> 2, t = lid & 3;
#pragma unroll
    for (int fn = 0; fn < 4; fn++) {
        const int col = n0 + nwarp + fn * 8 + t * 2;
        const float2 bv = *reinterpret_cast<const float2*>(bias + col);
#pragma unroll
        for (int fm = 0; fm < 2; fm++) {
            const int row = m0 + mwarp + fm * 16 + g;
#pragma unroll
            for (int h = 0; h < 2; h++) {
                float x = acc[fm][fn][h * 2 + 0] + bv.x;
                float y = acc[fm][fn][h * 2 + 1] + bv.y;
                x = fmaxf(x, 0.0f); y = fmaxf(y, 0.0f);
                const __nv_bfloat16 xh = __float2bfloat16(x);
                const __nv_bfloat16 yh = __float2bfloat16(y);
                const __nv_bfloat16 xl = __float2bfloat16(x - __bfloat162float(xh));
                const __nv_bfloat16 yl = __float2bfloat16(y - __bfloat162float(yh));
                const size_t o = (size_t)(row + h * 8) * DP + col;
                *reinterpret_cast<__nv_bfloat162*>(g_h_hi + o) = __nv_bfloat162(xh, yh);
                *reinterpret_cast<__nv_bfloat162*>(g_h_lo + o) = __nv_bfloat162(xl, yl);
            }
        }
    }
}

// =============================================================================
// GEMM2 (R8 structure): out[b][i][j] = (h_i . h_j)*clf_w + clf_b.
// Tile 128x128, 8 warps (64x32), 2-stage, triangular pairs + smem mirror.
// =============================================================================
#define S_TILE  8192
#define S_AH    0
#define S_AL    S_TILE
#define S_BH    (2 * S_TILE)
#define S_BL    (3 * S_TILE)
#define S_STAGE (4 * S_TILE)   // 32 KB; 2 stages = 64 KB

__device__ __forceinline__ void scores_fill(
    uint32_t sbase,
    const __nv_bfloat16* Ah, const __nv_bfloat16* Al,
    const __nv_bfloat16* Bh, const __nv_bfloat16* Bl,
    int kb, int tid)
{
#pragma unroll
    for (int i = 0; i < 2; i++) {
        const int idx = tid + i * 256;
        const int r = idx >> 2, c16 = idx & 3;
        const uint32_t sw = SWZ(r, c16);
        const size_t go = (size_t)r * DP + kb + c16 * 8;
        cp16(sbase + S_AH + sw, Ah + go);
        cp16(sbase + S_AL + sw, Al + go);
        cp16(sbase + S_BH + sw, Bh + go);
        cp16(sbase + S_BL + sw, Bl + go);
    }
}

__global__ __launch_bounds__(256, 2) void scores_kernel(
    const float* __restrict__ clf_w, const float* __restrict__ clf_b,
    float* __restrict__ out)
{
    extern __shared__ char sm[];
    const uint32_t sbase = smem_u32(sm);
    const int tid = threadIdx.x, lid = tid & 31, wid = tid >> 5;
    const int mwarp = (wid >> 2) * 64, nwarp = (wid & 3) * 32;
    const int bat = blockIdx.y;

    int tt = blockIdx.x, bi = 0;
    while (tt >= 16 - bi) { tt -= 16 - bi; bi++; }
    const int bj = bi + tt;

    const size_t hb = (size_t)bat * SEQ * DP;
    const __nv_bfloat16* Ah = g_h_hi + hb + (size_t)bi * 128 * DP;
    const __nv_bfloat16* Al = g_h_lo + hb + (size_t)bi * 128 * DP;
    const __nv_bfloat16* Bh = g_h_hi + hb + (size_t)bj * 128 * DP;
    const __nv_bfloat16* Bl = g_h_lo + hb + (size_t)bj * 128 * DP;

    float acc[4][4][4];
#pragma unroll
    for (int a = 0; a < 4; a++)
#pragma unroll
        for (int b = 0; b < 4; b++)
#pragma unroll
            for (int c = 0; c < 4; c++) acc[a][b][c] = 0.0f;

    const int rA = mwarp + (lid & 15), xA = (rA >> 1) & 3, cA = lid >> 4;
    const int rB = nwarp + ((lid >> 4) << 3) + (lid & 7), xB = (rB >> 1) & 3;
    const int cB = (lid >> 3) & 1;

    const int NC = DP / 32;   // 8
    scores_fill(sbase, Ah, Al, Bh, Bl, 0, tid);
    CP_COMMIT();
    for (int c = 0; c < NC; c++) {
        if (c + 1 < NC) {
            scores_fill(sbase + ((c + 1) & 1) * S_STAGE, Ah, Al, Bh, Bl,
                        (c + 1) * 32, tid);
            CP_COMMIT();
            CP_WAIT1();
        } else {
            CP_WAIT0();
        }
        __syncthreads();

        const uint32_t buf = sbase + (uint32_t)(c & 1) * S_STAGE;
#pragma unroll
        for (int kk = 0; kk < 2; kk++) {
            uint32_t bh[2][4], bl[2][4];
#pragma unroll
            for (int p = 0; p < 2; p++) {
                const uint32_t base = buf + (uint32_t)((rB + p * 16) * 64)
                                    + ((uint32_t)((kk * 2 + cB) ^ xB) << 4);
                ldsm4(bh[p], base + S_BH);
                ldsm4(bl[p], base + S_BL);
            }
#pragma unroll
            for (int fm = 0; fm < 4; fm++) {
                uint32_t ah[4], al[4];
                const uint32_t base = buf + (uint32_t)((rA + fm * 16) * 64)
                                    + ((uint32_t)((kk * 2 + cA) ^ xA) << 4);
                ldsm4(ah, base + S_AH);
                ldsm4(al, base + S_AL);
#pragma unroll
                for (int fn = 0; fn < 4; fn++) {
                    const uint32_t* bhp = &bh[fn >> 1][(fn & 1) * 2];
                    const uint32_t* blp = &bl[fn >> 1][(fn & 1) * 2];
                    mma_bf16(acc[fm][fn], ah, bhp);
                    mma_bf16(acc[fm][fn], ah, blp);
                    mma_bf16(acc[fm][fn], al, bhp);
                }
            }
        }
        __syncthreads();
    }

    const float scale = clf_w[0];
    const float beta  = clf_b[0];
    float* C = out + (size_t)bat * SEQ * SEQ;
    float (*Cs)[129] = reinterpret_cast<float (*)[129]>(sm);

    const int g = lid >> 2, t = lid & 3;
#pragma unroll
    for (int fm = 0; fm < 4; fm++)
#pragma unroll
        for (int fn = 0; fn < 4; fn++) {
            const int rl = mwarp + fm * 16 + g;
            const int cl = nwarp + fn * 8 + t * 2;
            const float v0 = acc[fm][fn][0] * scale + beta;
            const float v1 = acc[fm][fn][1] * scale + beta;
            const float v2 = acc[fm][fn][2] * scale + beta;
            const float v3 = acc[fm][fn][3] * scale + beta;
            *reinterpret_cast<float2*>(C + (size_t)(bi * 128 + rl) * SEQ + bj * 128 + cl)
                = make_float2(v0, v1);
            *reinterpret_cast<float2*>(C + (size_t)(bi * 128 + rl + 8) * SEQ + bj * 128 + cl)
                = make_float2(v2, v3);
            if (bi != bj) {
                Cs[rl][cl] = v0; Cs[rl][cl + 1] = v1;
                Cs[rl + 8][cl] = v2; Cs[rl + 8][cl + 1] = v3;
            }
        }

    if (bi != bj) {
        __syncthreads();
#pragma unroll 4
        for (int e = 0; e < 64; e++) {
            const int idx  = e * 256 + tid;
            const int cloc = idx >> 7;
            const int rloc = idx & 127;
            C[(size_t)(bj * 128 + cloc) * SEQ + bi * 128 + rloc] = Cs[rloc][cloc];
        }
    }
}

// =============================================================================
extern "C" void kernel_launch(void* const* d_in, const int* in_sizes, int n_in,
                              void* d_out, int out_size)
{
    const float* hidden = (const float*)d_in[0];
    const float* proj_w = (const float*)d_in[1];
    const float* proj_b = (const float*)d_in[2];
    const float* clf_w  = (const float*)d_in[3];
    const float* clf_b  = (const float*)d_in[4];
    float* out = (float*)d_out;

    __nv_bfloat16 *w_hi, *w_lo;
    cudaGetSymbolAddress((void**)&w_hi, g_w_hi);
    cudaGetSymbolAddress((void**)&w_lo, g_w_lo);

    split_kernel<<<64, 256>>>(proj_w, w_hi, w_lo);

    const int smem_proj = 2 * P_STAGE;        // 96 KB
    const int smem_sc   = 128 * 129 * 4;      // 66048 (covers 64 KB stages)
    cudaFuncSetAttribute(proj_kernel,
                         cudaFuncAttributeMaxDynamicSharedMemorySize, smem_proj);
    cudaFuncSetAttribute(scores_kernel,
                         cudaFuncAttributeMaxDynamicSharedMemorySize, smem_sc);

    dim3 g1(DP / 128, (NB * SEQ) / 64);       // (2, 128) = 256 CTAs
    proj_kernel<<<g1, 256, smem_proj>>>(hidden, proj_b);

    dim3 g2(136, NB);
    scores_kernel<<<g2, 256, smem_sc>>>(clf_w, clf_b, out);
}